// round 8
// baseline (speedup 1.0000x reference)
#include <cuda_runtime.h>
#include <cuda_bf16.h>
#include <math.h>
#include <stdint.h>

#define NPTS 512
#define DDIM 128
#define NMC  64
#define DENOM 16777216.0
#define NTASK 2048
#define GRID  296

// Scratch (static device globals — no allocation allowed)
__device__ uint8_t g_Xf8[(size_t)3*NMC*NPTS*DDIM];   // 12.6MB e4m3
__device__ float   g_norm[3*NMC*NPTS];
__device__ float   g_part[2*NMC*32*DDIM];            // per-block row-sum partials, sets A/C
__device__ double  g_accum;
__device__ unsigned g_count;

__device__ __forceinline__ uint32_t smem_u32(const void* p) {
    uint32_t a;
    asm("{ .reg .u64 t; cvta.to.shared.u64 t, %1; cvt.u32.u64 %0, t; }" : "=r"(a) : "l"(p));
    return a;
}

__device__ __forceinline__ void ldmatrix_x4(uint32_t* r, uint32_t addr) {
    asm volatile("ldmatrix.sync.aligned.m8n8.x4.shared.b16 {%0,%1,%2,%3}, [%4];"
                 : "=r"(r[0]), "=r"(r[1]), "=r"(r[2]), "=r"(r[3]) : "r"(addr));
}

__device__ __forceinline__ void mma_fp8(float* c, const uint32_t* a, const uint32_t* b) {
    asm volatile(
        "mma.sync.aligned.m16n8k32.row.col.f32.e4m3.e4m3.f32 "
        "{%0,%1,%2,%3}, {%4,%5,%6,%7}, {%8,%9}, {%0,%1,%2,%3};"
        : "+f"(c[0]), "+f"(c[1]), "+f"(c[2]), "+f"(c[3])
        : "r"(a[0]), "r"(a[1]), "r"(a[2]), "r"(a[3]), "r"(b[0]), "r"(b[1]));
}

__device__ __forceinline__ void cp16(uint32_t dst, const void* src) {
    asm volatile("cp.async.cg.shared.global [%0], [%1], 16;"
                 :: "r"(dst), "l"(__cvta_generic_to_global(src)) : "memory");
}
#define CP_COMMIT() asm volatile("cp.async.commit_group;" ::: "memory")
#define CP_WAIT1()  asm volatile("cp.async.wait_group 1;"  ::: "memory")

__device__ __forceinline__ uint32_t pack4_e4m3(float x0, float x1, float x2, float x3) {
    uint16_t lo, hi;
    asm("cvt.rn.satfinite.e4m3x2.f32 %0, %1, %2;" : "=h"(lo) : "f"(x1), "f"(x0));
    asm("cvt.rn.satfinite.e4m3x2.f32 %0, %1, %2;" : "=h"(hi) : "f"(x3), "f"(x2));
    return (uint32_t)lo | ((uint32_t)hi << 16);
}

// ---- k_gen: x = mu + sigma*eps -> e4m3 X, fp32 norms, A/C row-sum partials.
// Block = 8 warps x 2 rows each = 16 rows of one (s, m). Grid = 3*64*32.
__global__ __launch_bounds__(256) void k_gen(
        const float* __restrict__ mu, const float* __restrict__ sigma,
        const float* __restrict__ epsA, const float* __restrict__ epsB,
        const float* __restrict__ epsC) {
    if (blockIdx.x == 0 && threadIdx.x == 0) { g_accum = 0.0; g_count = 0u; }
    int b  = blockIdx.x;
    int s  = b / (NMC * 32);
    int m  = (b / 32) % NMC;
    int ng = b % 32;
    int tid  = threadIdx.x;
    int wid  = tid >> 5;
    int lane = tid & 31;
    int n0 = ng * 16 + wid * 2;

    const float* eps = (s == 0) ? epsA : (s == 1) ? epsB : epsC;
    // Two rows per warp: 6 independent LDG.128 in flight.
    float4 a0 = ((const float4*)(mu    + (size_t)(s*NPTS + n0)*DDIM))[lane];
    float4 a1 = ((const float4*)(mu    + (size_t)(s*NPTS + n0 + 1)*DDIM))[lane];
    float4 g0 = ((const float4*)(sigma + (size_t)(s*NPTS + n0)*DDIM))[lane];
    float4 g1 = ((const float4*)(sigma + (size_t)(s*NPTS + n0 + 1)*DDIM))[lane];
    float4 e0 = ((const float4*)(eps   + ((size_t)m*NPTS + n0)*DDIM))[lane];
    float4 e1 = ((const float4*)(eps   + ((size_t)m*NPTS + n0 + 1)*DDIM))[lane];
    float4 x0, x1;
    x0.x = fmaf(g0.x, e0.x, a0.x); x0.y = fmaf(g0.y, e0.y, a0.y);
    x0.z = fmaf(g0.z, e0.z, a0.z); x0.w = fmaf(g0.w, e0.w, a0.w);
    x1.x = fmaf(g1.x, e1.x, a1.x); x1.y = fmaf(g1.y, e1.y, a1.y);
    x1.z = fmaf(g1.z, e1.z, a1.z); x1.w = fmaf(g1.w, e1.w, a1.w);
    size_t row0 = (size_t)(s*NMC + m)*NPTS + n0;
    ((uint32_t*)(g_Xf8 + row0*DDIM))[lane]          = pack4_e4m3(x0.x, x0.y, x0.z, x0.w);
    ((uint32_t*)(g_Xf8 + (row0 + 1)*DDIM))[lane]    = pack4_e4m3(x1.x, x1.y, x1.z, x1.w);
    float s0 = x0.x*x0.x + x0.y*x0.y + x0.z*x0.z + x0.w*x0.w;
    float s1 = x1.x*x1.x + x1.y*x1.y + x1.z*x1.z + x1.w*x1.w;
    #pragma unroll
    for (int o = 16; o; o >>= 1) {
        s0 += __shfl_xor_sync(0xffffffffu, s0, o);
        s1 += __shfl_xor_sync(0xffffffffu, s1, o);
    }
    if (lane == 0) { g_norm[row0] = s0; g_norm[row0 + 1] = s1; }

    if (s != 1) {   // partial row-sum vectors for the analytic pos term
        __shared__ float sx[16 * DDIM];
        ((float4*)sx)[(wid*2)     * 32 + lane] = x0;
        ((float4*)sx)[(wid*2 + 1) * 32 + lane] = x1;
        __syncthreads();
        if (tid < DDIM) {
            float acc = 0.0f;
            #pragma unroll
            for (int ww = 0; ww < 16; ww++) acc += sx[ww * DDIM + tid];
            int si = (s == 0) ? 0 : 1;
            g_part[((si*NMC + m)*32 + ng)*DDIM + tid] = acc;
        }
    }
}

// Per-buffer layout: A[0:16384) B[16384:32768) xn[32768:33280) yn[33280:33792)
#define BUFSZ 33792
#define SM_TOTAL (2*BUFSZ)

// Neg tasks only: t bit0 -> pair (0=dBA cs=0, 1=dBC cs=2); rows always set B.
__device__ __forceinline__ void prefetch_task(int t, uint32_t sbuf, int tid) {
    int pp = t & 1;  int r1 = t >> 1;
    int m  = r1 & 63; int r2 = r1 >> 6;
    int bx = r2 & 3;  int by = r2 >> 2;
    int cs = pp ? 2 : 0;
    const uint8_t* Xg = g_Xf8 + ((size_t)(1*NMC + m)*NPTS + by*128) * DDIM;
    const uint8_t* Yg = g_Xf8 + ((size_t)(cs*NMC + m)*NPTS + bx*128) * DDIM;
    #pragma unroll
    for (int i2 = 0; i2 < 4; i2++) {
        int f = i2 * 256 + tid;               // 1024 chunks per tile
        int row = f >> 3, c = f & 7;
        uint32_t dsto = (uint32_t)(row * 128 + ((c ^ (row & 7)) << 4));
        cp16(sbuf + dsto, Xg + row * DDIM + c * 16);
        cp16(sbuf + 16384u + dsto, Yg + row * DDIM + c * 16);
    }
    if (tid < 32) {
        const float* nX = g_norm + (size_t)(1*NMC + m)*NPTS + by*128;
        cp16(sbuf + 32768u + tid*16, nX + tid*4);
    } else if (tid < 64) {
        const float* nY = g_norm + (size_t)(cs*NMC + m)*NPTS + bx*128;
        cp16(sbuf + 33280u + (tid-32)*16, nY + (tid-32)*4);
    }
}

// Persistent fp8 warp-MMA Gram GEMM, neg terms; CTAs 0..63 also fold in the
// analytic pos term for m = blockIdx.x while the first prefetch is in flight.
__global__ __launch_bounds__(256, 2) void k_dist(float* __restrict__ out) {
    extern __shared__ char smem[];
    __shared__ float red[8];
    uint32_t sb = smem_u32(smem);
    int tid  = threadIdx.x;
    int lane = tid & 31;
    int w    = tid >> 5;
    int warp_m = w & 3;     // 4 warps over M (32 rows each)
    int warp_n = w >> 2;    // 2 warps over N (64 cols each)

    prefetch_task((int)blockIdx.x, sb, tid);
    CP_COMMIT();

    // ---- pos term (exact, fp32): 512*(sum||xA||^2 + sum||xC||^2) - 2*SA.SC
    if (blockIdx.x < NMC) {
        int m = blockIdx.x;
        float u = 0.0f;
        if (tid < DDIM) {
            float sa = 0.0f, sc = 0.0f;
            #pragma unroll 4
            for (int ng = 0; ng < 32; ng++) {
                sa += g_part[((0*NMC + m)*32 + ng)*DDIM + tid];
                sc += g_part[((1*NMC + m)*32 + ng)*DDIM + tid];
            }
            u = -2.0f * sa * sc;
        }
        float ns = 0.0f;
        for (int i = tid; i < NPTS; i += 256) {
            ns += g_norm[(size_t)(0*NMC + m)*NPTS + i]
                + g_norm[(size_t)(2*NMC + m)*NPTS + i];
        }
        u = fmaf(512.0f, ns, u);
        #pragma unroll
        for (int o = 16; o; o >>= 1) u += __shfl_xor_sync(0xffffffffu, u, o);
        if (lane == 0) red[w] = u;
        __syncthreads();
        if (tid == 0) {
            float v = red[0] + red[1] + red[2] + red[3]
                    + red[4] + red[5] + red[6] + red[7];
            atomicAdd(&g_accum, (double)v);
        }
        __syncthreads();
    }

    float local = 0.0f;
    int it = 0;
    for (int t = (int)blockIdx.x; t < NTASK; t += GRID, it ^= 1) {
        int nxt = t + GRID;
        if (nxt < NTASK) prefetch_task(nxt, sb + (uint32_t)(it ^ 1) * BUFSZ, tid);
        CP_COMMIT();
        CP_WAIT1();
        __syncthreads();

        uint32_t bufA = sb + (uint32_t)it * BUFSZ;
        uint32_t bufB = bufA + 16384u;
        const float* xns = (const float*)(smem + it * BUFSZ + 32768);
        const float* yns = (const float*)(smem + it * BUFSZ + 33280);

        // Threshold-folded accumulator init: acc = -(px_i + py_j) with
        // px = 0.5*xn - 1, py = 0.5*yn - 1. Guard later: acc > 0.
        float acc[2][8][4];
        {
            float npy[8][2];
            #pragma unroll
            for (int nt = 0; nt < 8; nt++) {
                int nbase = warp_n * 64 + nt * 8 + (lane & 3) * 2;
                npy[nt][0] = fmaf(yns[nbase],     -0.5f, 1.0f);
                npy[nt][1] = fmaf(yns[nbase + 1], -0.5f, 1.0f);
            }
            #pragma unroll
            for (int mt = 0; mt < 2; mt++) {
                int mbase = warp_m * 32 + mt * 16 + (lane >> 2);
                float npx0 = fmaf(xns[mbase],     -0.5f, 1.0f);
                float npx1 = fmaf(xns[mbase + 8], -0.5f, 1.0f);
                #pragma unroll
                for (int nt = 0; nt < 8; nt++) {
                    acc[mt][nt][0] = npx0 + npy[nt][0];
                    acc[mt][nt][1] = npx0 + npy[nt][1];
                    acc[mt][nt][2] = npx1 + npy[nt][0];
                    acc[mt][nt][3] = npx1 + npy[nt][1];
                }
            }
        }

        #pragma unroll
        for (int ks = 0; ks < 4; ks++) {
            uint32_t a[2][4];
            #pragma unroll
            for (int mt = 0; mt < 2; mt++) {
                int r  = warp_m * 32 + mt * 16 + (lane & 15);
                int kb = ks * 32 + (lane >> 4) * 16;
                uint32_t addr = bufA + (uint32_t)(r * 128 + (((kb >> 4) ^ (r & 7)) << 4));
                ldmatrix_x4(a[mt], addr);
            }
            #pragma unroll
            for (int nt2 = 0; nt2 < 4; nt2++) {
                int r  = warp_n * 64 + nt2 * 16 + (lane & 7) + ((lane >> 4) << 3);
                int kb = ks * 32 + ((lane >> 3) & 1) * 16;
                uint32_t addr = bufB + (uint32_t)(r * 128 + (((kb >> 4) ^ (r & 7)) << 4));
                uint32_t tb[4];
                ldmatrix_x4(tb, addr);
                mma_fp8(acc[0][nt2*2],     a[0], &tb[0]);
                mma_fp8(acc[0][nt2*2 + 1], a[0], &tb[2]);
                mma_fp8(acc[1][nt2*2],     a[1], &tb[0]);
                mma_fp8(acc[1][nt2*2 + 1], a[1], &tb[2]);
            }
        }

        // Epilogue: relu(2-d)>0 iff acc > 0; d2 = 4 - 2*acc.
        #pragma unroll
        for (int mt = 0; mt < 2; mt++)
            #pragma unroll
            for (int nt = 0; nt < 8; nt++)
                #pragma unroll
                for (int r = 0; r < 4; r++) {
                    float av = acc[mt][nt][r];
                    if (av > 0.0f) {
                        float d2 = fmaf(av, -2.0f, 4.0f);
                        float q = 2.0f - sqrtf(fmaxf(d2, 1e-12f));
                        local += q * q;
                    }
                }
        __syncthreads();
    }

    #pragma unroll
    for (int o = 16; o; o >>= 1) local += __shfl_xor_sync(0xffffffffu, local, o);
    if (lane == 0) red[w] = local;
    __syncthreads();
    if (tid == 0) {
        float v = red[0] + red[1] + red[2] + red[3]
                + red[4] + red[5] + red[6] + red[7];
        atomicAdd(&g_accum, (double)v);
        __threadfence();
        unsigned c = atomicAdd(&g_count, 1u);
        if (c == GRID - 1) {
            double total = atomicAdd(&g_accum, 0.0);
            out[0] = (float)(total * (1.0 / DENOM));
        }
    }
}

extern "C" void kernel_launch(void* const* d_in, const int* in_sizes, int n_in,
                              void* d_out, int out_size) {
    const float* mu    = (const float*)d_in[0];
    const float* sigma = (const float*)d_in[1];
    const float* epsA  = (const float*)d_in[2];
    const float* epsB  = (const float*)d_in[3];
    const float* epsC  = (const float*)d_in[4];
    (void)in_sizes; (void)n_in; (void)out_size;

    cudaFuncSetAttribute(k_dist, cudaFuncAttributeMaxDynamicSharedMemorySize, SM_TOTAL);

    k_gen<<<3*NMC*32, 256>>>(mu, sigma, epsA, epsB, epsC);
    k_dist<<<GRID, 256, SM_TOTAL>>>((float*)d_out);
}

// round 9
// speedup vs baseline: 2.2652x; 2.2652x over previous
#include <cuda_runtime.h>
#include <cuda_bf16.h>
#include <math.h>
#include <stdint.h>

#define NPTS 512
#define DDIM 128
#define NMC  64
#define DENOM 16777216.0
#define NTASK 2048
#define GRID  296

// Scratch (static device globals — no allocation allowed)
__device__ uint8_t g_Xf8[(size_t)3*NMC*NPTS*DDIM];   // 12.6MB e4m3
__device__ float   g_norm[3*NMC*NPTS];
__device__ float   g_part[2*NMC*32*DDIM];            // per-block row-sum partials, sets A/C
__device__ double  g_accum;
__device__ unsigned g_count;

__device__ __forceinline__ uint32_t smem_u32(const void* p) {
    uint32_t a;
    asm("{ .reg .u64 t; cvta.to.shared.u64 t, %1; cvt.u32.u64 %0, t; }" : "=r"(a) : "l"(p));
    return a;
}

__device__ __forceinline__ void ldmatrix_x4(uint32_t* r, uint32_t addr) {
    asm volatile("ldmatrix.sync.aligned.m8n8.x4.shared.b16 {%0,%1,%2,%3}, [%4];"
                 : "=r"(r[0]), "=r"(r[1]), "=r"(r[2]), "=r"(r[3]) : "r"(addr));
}

__device__ __forceinline__ void mma_fp8(float* c, const uint32_t* a, const uint32_t* b) {
    asm volatile(
        "mma.sync.aligned.m16n8k32.row.col.f32.e4m3.e4m3.f32 "
        "{%0,%1,%2,%3}, {%4,%5,%6,%7}, {%8,%9}, {%0,%1,%2,%3};"
        : "+f"(c[0]), "+f"(c[1]), "+f"(c[2]), "+f"(c[3])
        : "r"(a[0]), "r"(a[1]), "r"(a[2]), "r"(a[3]), "r"(b[0]), "r"(b[1]));
}

__device__ __forceinline__ void cp16(uint32_t dst, const void* src) {
    asm volatile("cp.async.cg.shared.global [%0], [%1], 16;"
                 :: "r"(dst), "l"(__cvta_generic_to_global(src)) : "memory");
}
#define CP_COMMIT() asm volatile("cp.async.commit_group;" ::: "memory")
#define CP_WAIT1()  asm volatile("cp.async.wait_group 1;"  ::: "memory")

__device__ __forceinline__ uint32_t pack4_e4m3(float x0, float x1, float x2, float x3) {
    uint16_t lo, hi;
    asm("cvt.rn.satfinite.e4m3x2.f32 %0, %1, %2;" : "=h"(lo) : "f"(x1), "f"(x0));
    asm("cvt.rn.satfinite.e4m3x2.f32 %0, %1, %2;" : "=h"(hi) : "f"(x3), "f"(x2));
    return (uint32_t)lo | ((uint32_t)hi << 16);
}

// ---- k_gen: x = mu + sigma*eps -> e4m3 X, fp32 norms, A/C row-sum partials.
// Block = 8 warps x 2 rows each = 16 rows of one (s, m). Grid = 3*64*32.
__global__ __launch_bounds__(256) void k_gen(
        const float* __restrict__ mu, const float* __restrict__ sigma,
        const float* __restrict__ epsA, const float* __restrict__ epsB,
        const float* __restrict__ epsC) {
    if (blockIdx.x == 0 && threadIdx.x == 0) { g_accum = 0.0; g_count = 0u; }
    int b  = blockIdx.x;
    int s  = b / (NMC * 32);
    int m  = (b / 32) % NMC;
    int ng = b % 32;
    int tid  = threadIdx.x;
    int wid  = tid >> 5;
    int lane = tid & 31;
    int n0 = ng * 16 + wid * 2;

    const float* eps = (s == 0) ? epsA : (s == 1) ? epsB : epsC;
    float4 a0 = ((const float4*)(mu    + (size_t)(s*NPTS + n0)*DDIM))[lane];
    float4 a1 = ((const float4*)(mu    + (size_t)(s*NPTS + n0 + 1)*DDIM))[lane];
    float4 g0 = ((const float4*)(sigma + (size_t)(s*NPTS + n0)*DDIM))[lane];
    float4 g1 = ((const float4*)(sigma + (size_t)(s*NPTS + n0 + 1)*DDIM))[lane];
    float4 e0 = ((const float4*)(eps   + ((size_t)m*NPTS + n0)*DDIM))[lane];
    float4 e1 = ((const float4*)(eps   + ((size_t)m*NPTS + n0 + 1)*DDIM))[lane];
    float4 x0, x1;
    x0.x = fmaf(g0.x, e0.x, a0.x); x0.y = fmaf(g0.y, e0.y, a0.y);
    x0.z = fmaf(g0.z, e0.z, a0.z); x0.w = fmaf(g0.w, e0.w, a0.w);
    x1.x = fmaf(g1.x, e1.x, a1.x); x1.y = fmaf(g1.y, e1.y, a1.y);
    x1.z = fmaf(g1.z, e1.z, a1.z); x1.w = fmaf(g1.w, e1.w, a1.w);
    size_t row0 = (size_t)(s*NMC + m)*NPTS + n0;
    ((uint32_t*)(g_Xf8 + row0*DDIM))[lane]       = pack4_e4m3(x0.x, x0.y, x0.z, x0.w);
    ((uint32_t*)(g_Xf8 + (row0 + 1)*DDIM))[lane] = pack4_e4m3(x1.x, x1.y, x1.z, x1.w);
    float s0 = x0.x*x0.x + x0.y*x0.y + x0.z*x0.z + x0.w*x0.w;
    float s1 = x1.x*x1.x + x1.y*x1.y + x1.z*x1.z + x1.w*x1.w;
    #pragma unroll
    for (int o = 16; o; o >>= 1) {
        s0 += __shfl_xor_sync(0xffffffffu, s0, o);
        s1 += __shfl_xor_sync(0xffffffffu, s1, o);
    }
    if (lane == 0) { g_norm[row0] = s0; g_norm[row0 + 1] = s1; }

    if (s != 1) {   // partial row-sum vectors for the analytic pos term
        __shared__ float sx[16 * DDIM];
        ((float4*)sx)[(wid*2)     * 32 + lane] = x0;
        ((float4*)sx)[(wid*2 + 1) * 32 + lane] = x1;
        __syncthreads();
        if (tid < DDIM) {
            float acc = 0.0f;
            #pragma unroll
            for (int ww = 0; ww < 16; ww++) acc += sx[ww * DDIM + tid];
            int si = (s == 0) ? 0 : 1;
            g_part[((si*NMC + m)*32 + ng)*DDIM + tid] = acc;
        }
    }
}

// Per-buffer layout: A[0:16384) B[16384:32768) xn[32768:33280) yn[33280:33792)
#define BUFSZ 33792
#define SM_TOTAL (2*BUFSZ)

// Neg tasks only: t bit0 -> pair (0=dBA cs=0, 1=dBC cs=2); rows always set B.
__device__ __forceinline__ void prefetch_task(int t, uint32_t sbuf, int tid) {
    int pp = t & 1;  int r1 = t >> 1;
    int m  = r1 & 63; int r2 = r1 >> 6;
    int bx = r2 & 3;  int by = r2 >> 2;
    int cs = pp ? 2 : 0;
    const uint8_t* Xg = g_Xf8 + ((size_t)(1*NMC + m)*NPTS + by*128) * DDIM;
    const uint8_t* Yg = g_Xf8 + ((size_t)(cs*NMC + m)*NPTS + bx*128) * DDIM;
    #pragma unroll
    for (int i2 = 0; i2 < 4; i2++) {
        int f = i2 * 256 + tid;               // 1024 chunks per tile
        int row = f >> 3, c = f & 7;
        uint32_t dsto = (uint32_t)(row * 128 + ((c ^ (row & 7)) << 4));
        cp16(sbuf + dsto, Xg + row * DDIM + c * 16);
        cp16(sbuf + 16384u + dsto, Yg + row * DDIM + c * 16);
    }
    if (tid < 32) {
        const float* nX = g_norm + (size_t)(1*NMC + m)*NPTS + by*128;
        cp16(sbuf + 32768u + tid*16, nX + tid*4);
    } else if (tid < 64) {
        const float* nY = g_norm + (size_t)(cs*NMC + m)*NPTS + bx*128;
        cp16(sbuf + 33280u + (tid-32)*16, nY + (tid-32)*4);
    }
}

// Persistent fp8 warp-MMA Gram GEMM (neg terms). CTAs 0..63 fold in the
// analytic pos term while the first prefetch is in flight. Epilogue keeps
// R7's structure: acc init to zero; thresholds computed after MMA (no reg
// pressure before the MMA loop -> no spills at the 128-reg cap).
__global__ __launch_bounds__(256, 2) void k_dist(float* __restrict__ out) {
    extern __shared__ char smem[];
    __shared__ float red[8];
    uint32_t sb = smem_u32(smem);
    int tid  = threadIdx.x;
    int lane = tid & 31;
    int w    = tid >> 5;
    int warp_m = w & 3;     // 4 warps over M (32 rows each)
    int warp_n = w >> 2;    // 2 warps over N (64 cols each)

    prefetch_task((int)blockIdx.x, sb, tid);
    CP_COMMIT();

    // ---- pos term (exact, fp32): 512*(sum||xA||^2 + sum||xC||^2) - 2*SA.SC
    if (blockIdx.x < NMC) {
        int m = blockIdx.x;
        float u = 0.0f;
        if (tid < DDIM) {
            float sa = 0.0f, sc = 0.0f;
            #pragma unroll 4
            for (int ng = 0; ng < 32; ng++) {
                sa += g_part[((0*NMC + m)*32 + ng)*DDIM + tid];
                sc += g_part[((1*NMC + m)*32 + ng)*DDIM + tid];
            }
            u = -2.0f * sa * sc;
        }
        float ns = 0.0f;
        for (int i = tid; i < NPTS; i += 256) {
            ns += g_norm[(size_t)(0*NMC + m)*NPTS + i]
                + g_norm[(size_t)(2*NMC + m)*NPTS + i];
        }
        u = fmaf(512.0f, ns, u);
        #pragma unroll
        for (int o = 16; o; o >>= 1) u += __shfl_xor_sync(0xffffffffu, u, o);
        if (lane == 0) red[w] = u;
        __syncthreads();
        if (tid == 0) {
            float v = red[0] + red[1] + red[2] + red[3]
                    + red[4] + red[5] + red[6] + red[7];
            atomicAdd(&g_accum, (double)v);
        }
        __syncthreads();
    }

    float local = 0.0f;
    int it = 0;
    for (int t = (int)blockIdx.x; t < NTASK; t += GRID, it ^= 1) {
        int nxt = t + GRID;
        if (nxt < NTASK) prefetch_task(nxt, sb + (uint32_t)(it ^ 1) * BUFSZ, tid);
        CP_COMMIT();
        CP_WAIT1();
        __syncthreads();

        uint32_t bufA = sb + (uint32_t)it * BUFSZ;
        uint32_t bufB = bufA + 16384u;
        const float* xns = (const float*)(smem + it * BUFSZ + 32768);
        const float* yns = (const float*)(smem + it * BUFSZ + 33280);

        float acc[2][8][4];
        #pragma unroll
        for (int mt = 0; mt < 2; mt++)
            #pragma unroll
            for (int nt = 0; nt < 8; nt++)
                #pragma unroll
                for (int r = 0; r < 4; r++) acc[mt][nt][r] = 0.0f;

        #pragma unroll
        for (int ks = 0; ks < 4; ks++) {
            uint32_t a[2][4];
            #pragma unroll
            for (int mt = 0; mt < 2; mt++) {
                int r  = warp_m * 32 + mt * 16 + (lane & 15);
                int kb = ks * 32 + (lane >> 4) * 16;
                uint32_t addr = bufA + (uint32_t)(r * 128 + (((kb >> 4) ^ (r & 7)) << 4));
                ldmatrix_x4(a[mt], addr);
            }
            #pragma unroll
            for (int nt2 = 0; nt2 < 4; nt2++) {
                int r  = warp_n * 64 + nt2 * 16 + (lane & 7) + ((lane >> 4) << 3);
                int kb = ks * 32 + ((lane >> 3) & 1) * 16;
                uint32_t addr = bufB + (uint32_t)(r * 128 + (((kb >> 4) ^ (r & 7)) << 4));
                uint32_t tb[4];
                ldmatrix_x4(tb, addr);
                mma_fp8(acc[0][nt2*2],     a[0], &tb[0]);
                mma_fp8(acc[0][nt2*2 + 1], a[0], &tb[2]);
                mma_fp8(acc[1][nt2*2],     a[1], &tb[0]);
                mma_fp8(acc[1][nt2*2 + 1], a[1], &tb[2]);
            }
        }

        // Epilogue (R7 form): relu(2-d)>0 iff acc > px+py,
        // px = 0.5*xn-1, py = 0.5*yn-1; d2 = 2*((px+py)-acc)+4.
        float py[8][2];
        #pragma unroll
        for (int nt = 0; nt < 8; nt++) {
            int nbase = warp_n * 64 + nt * 8 + (lane & 3) * 2;
            py[nt][0] = fmaf(yns[nbase],     0.5f, -1.0f);
            py[nt][1] = fmaf(yns[nbase + 1], 0.5f, -1.0f);
        }
        #pragma unroll
        for (int mt = 0; mt < 2; mt++) {
            int mbase = warp_m * 32 + mt * 16 + (lane >> 2);
            float px0 = fmaf(xns[mbase],     0.5f, -1.0f);
            float px1 = fmaf(xns[mbase + 8], 0.5f, -1.0f);
            #pragma unroll
            for (int nt = 0; nt < 8; nt++) {
                float t00 = px0 + py[nt][0];
                float t01 = px0 + py[nt][1];
                float t10 = px1 + py[nt][0];
                float t11 = px1 + py[nt][1];
                if (acc[mt][nt][0] > t00) { float d2 = 2.0f*(t00 - acc[mt][nt][0]) + 4.0f; float q = 2.0f - sqrtf(fmaxf(d2, 1e-12f)); local += q*q; }
                if (acc[mt][nt][1] > t01) { float d2 = 2.0f*(t01 - acc[mt][nt][1]) + 4.0f; float q = 2.0f - sqrtf(fmaxf(d2, 1e-12f)); local += q*q; }
                if (acc[mt][nt][2] > t10) { float d2 = 2.0f*(t10 - acc[mt][nt][2]) + 4.0f; float q = 2.0f - sqrtf(fmaxf(d2, 1e-12f)); local += q*q; }
                if (acc[mt][nt][3] > t11) { float d2 = 2.0f*(t11 - acc[mt][nt][3]) + 4.0f; float q = 2.0f - sqrtf(fmaxf(d2, 1e-12f)); local += q*q; }
            }
        }
        __syncthreads();
    }

    #pragma unroll
    for (int o = 16; o; o >>= 1) local += __shfl_xor_sync(0xffffffffu, local, o);
    if (lane == 0) red[w] = local;
    __syncthreads();
    if (tid == 0) {
        float v = red[0] + red[1] + red[2] + red[3]
                + red[4] + red[5] + red[6] + red[7];
        atomicAdd(&g_accum, (double)v);
        __threadfence();
        unsigned c = atomicAdd(&g_count, 1u);
        if (c == GRID - 1) {
            double total = atomicAdd(&g_accum, 0.0);
            out[0] = (float)(total * (1.0 / DENOM));
        }
    }
}

extern "C" void kernel_launch(void* const* d_in, const int* in_sizes, int n_in,
                              void* d_out, int out_size) {
    const float* mu    = (const float*)d_in[0];
    const float* sigma = (const float*)d_in[1];
    const float* epsA  = (const float*)d_in[2];
    const float* epsB  = (const float*)d_in[3];
    const float* epsC  = (const float*)d_in[4];
    (void)in_sizes; (void)n_in; (void)out_size;

    cudaFuncSetAttribute(k_dist, cudaFuncAttributeMaxDynamicSharedMemorySize, SM_TOTAL);

    k_gen<<<3*NMC*32, 256>>>(mu, sigma, epsA, epsB, epsC);
    k_dist<<<GRID, 256, SM_TOTAL>>>((float*)d_out);
}

// round 10
// speedup vs baseline: 2.7949x; 1.2338x over previous
#include <cuda_runtime.h>
#include <cuda_bf16.h>
#include <math.h>
#include <stdint.h>

#define NPTS 512
#define DDIM 128
#define NMC  64
#define DENOM 16777216.0
#define NTASK 2048
#define GRID  296

// Scratch (static device globals — no allocation allowed)
__device__ uint8_t g_Xf8[(size_t)3*NMC*NPTS*DDIM];   // 12.6MB e4m3
__device__ float   g_norm[3*NMC*NPTS];
__device__ float   g_part[2*NMC*16*DDIM];            // per-block row-sum partials, sets A/C
__device__ double  g_accum;
__device__ unsigned g_count;

__device__ __forceinline__ uint32_t smem_u32(const void* p) {
    uint32_t a;
    asm("{ .reg .u64 t; cvta.to.shared.u64 t, %1; cvt.u32.u64 %0, t; }" : "=r"(a) : "l"(p));
    return a;
}

__device__ __forceinline__ void ldmatrix_x4(uint32_t* r, uint32_t addr) {
    asm volatile("ldmatrix.sync.aligned.m8n8.x4.shared.b16 {%0,%1,%2,%3}, [%4];"
                 : "=r"(r[0]), "=r"(r[1]), "=r"(r[2]), "=r"(r[3]) : "r"(addr));
}

__device__ __forceinline__ void mma_fp8(float* c, const uint32_t* a, const uint32_t* b) {
    asm volatile(
        "mma.sync.aligned.m16n8k32.row.col.f32.e4m3.e4m3.f32 "
        "{%0,%1,%2,%3}, {%4,%5,%6,%7}, {%8,%9}, {%0,%1,%2,%3};"
        : "+f"(c[0]), "+f"(c[1]), "+f"(c[2]), "+f"(c[3])
        : "r"(a[0]), "r"(a[1]), "r"(a[2]), "r"(a[3]), "r"(b[0]), "r"(b[1]));
}

__device__ __forceinline__ void cp16(uint32_t dst, const void* src) {
    asm volatile("cp.async.cg.shared.global [%0], [%1], 16;"
                 :: "r"(dst), "l"(__cvta_generic_to_global(src)) : "memory");
}
#define CP_COMMIT() asm volatile("cp.async.commit_group;" ::: "memory")
#define CP_WAIT1()  asm volatile("cp.async.wait_group 1;"  ::: "memory")

__device__ __forceinline__ uint32_t pack4_e4m3(float x0, float x1, float x2, float x3) {
    uint16_t lo, hi;
    asm("cvt.rn.satfinite.e4m3x2.f32 %0, %1, %2;" : "=h"(lo) : "f"(x1), "f"(x0));
    asm("cvt.rn.satfinite.e4m3x2.f32 %0, %1, %2;" : "=h"(hi) : "f"(x3), "f"(x2));
    return (uint32_t)lo | ((uint32_t)hi << 16);
}

// ---- k_gen: x = mu + sigma*eps -> e4m3 X, fp32 norms, A/C row-sum partials.
// Block = 8 warps x 4 rows each = 32 rows of one (s, m). Grid = 3*64*16.
__global__ __launch_bounds__(256) void k_gen(
        const float* __restrict__ mu, const float* __restrict__ sigma,
        const float* __restrict__ epsA, const float* __restrict__ epsB,
        const float* __restrict__ epsC) {
    if (blockIdx.x == 0 && threadIdx.x == 0) { g_accum = 0.0; g_count = 0u; }
    int b  = blockIdx.x;
    int s  = b / (NMC * 16);
    int m  = (b / 16) % NMC;
    int ng = b % 16;
    int tid  = threadIdx.x;
    int wid  = tid >> 5;
    int lane = tid & 31;
    int n0 = ng * 32 + wid * 4;

    const float* eps = (s == 0) ? epsA : (s == 1) ? epsB : epsC;
    float4 a[4], g[4], e[4], x[4];
    #pragma unroll
    for (int r = 0; r < 4; r++) {
        a[r] = ((const float4*)(mu    + (size_t)(s*NPTS + n0 + r)*DDIM))[lane];
        g[r] = ((const float4*)(sigma + (size_t)(s*NPTS + n0 + r)*DDIM))[lane];
        e[r] = ((const float4*)(eps   + ((size_t)m*NPTS + n0 + r)*DDIM))[lane];
    }
    float ss[4];
    size_t row0 = (size_t)(s*NMC + m)*NPTS + n0;
    #pragma unroll
    for (int r = 0; r < 4; r++) {
        x[r].x = fmaf(g[r].x, e[r].x, a[r].x);
        x[r].y = fmaf(g[r].y, e[r].y, a[r].y);
        x[r].z = fmaf(g[r].z, e[r].z, a[r].z);
        x[r].w = fmaf(g[r].w, e[r].w, a[r].w);
        ((uint32_t*)(g_Xf8 + (row0 + r)*DDIM))[lane] =
            pack4_e4m3(x[r].x, x[r].y, x[r].z, x[r].w);
        ss[r] = x[r].x*x[r].x + x[r].y*x[r].y + x[r].z*x[r].z + x[r].w*x[r].w;
    }
    #pragma unroll
    for (int o = 16; o; o >>= 1) {
        #pragma unroll
        for (int r = 0; r < 4; r++) ss[r] += __shfl_xor_sync(0xffffffffu, ss[r], o);
    }
    if (lane == 0) {
        #pragma unroll
        for (int r = 0; r < 4; r++) g_norm[row0 + r] = ss[r];
    }

    if (s != 1) {   // partial row-sum vectors for the analytic pos term
        __shared__ float sx[32 * DDIM];
        #pragma unroll
        for (int r = 0; r < 4; r++)
            ((float4*)sx)[(wid*4 + r) * 32 + lane] = x[r];
        __syncthreads();
        if (tid < DDIM) {
            float acc = 0.0f;
            #pragma unroll
            for (int ww = 0; ww < 32; ww++) acc += sx[ww * DDIM + tid];
            int si = (s == 0) ? 0 : 1;
            g_part[((si*NMC + m)*16 + ng)*DDIM + tid] = acc;
        }
    }
}

// Per-buffer layout: A[0:16384) B[16384:32768) xn[32768:33280) yn[33280:33792)
#define BUFSZ 33792
#define SM_TOTAL (2*BUFSZ)

// Neg tasks only: t bit0 -> pair (0=dBA cs=0, 1=dBC cs=2); rows always set B.
__device__ __forceinline__ void prefetch_task(int t, uint32_t sbuf, int tid) {
    int pp = t & 1;  int r1 = t >> 1;
    int m  = r1 & 63; int r2 = r1 >> 6;
    int bx = r2 & 3;  int by = r2 >> 2;
    int cs = pp ? 2 : 0;
    const uint8_t* Xg = g_Xf8 + ((size_t)(1*NMC + m)*NPTS + by*128) * DDIM;
    const uint8_t* Yg = g_Xf8 + ((size_t)(cs*NMC + m)*NPTS + bx*128) * DDIM;
    #pragma unroll
    for (int i2 = 0; i2 < 4; i2++) {
        int f = i2 * 256 + tid;               // 1024 chunks per tile
        int row = f >> 3, c = f & 7;
        uint32_t dsto = (uint32_t)(row * 128 + ((c ^ (row & 7)) << 4));
        cp16(sbuf + dsto, Xg + row * DDIM + c * 16);
        cp16(sbuf + 16384u + dsto, Yg + row * DDIM + c * 16);
    }
    if (tid < 32) {
        const float* nX = g_norm + (size_t)(1*NMC + m)*NPTS + by*128;
        cp16(sbuf + 32768u + tid*16, nX + tid*4);
    } else if (tid < 64) {
        const float* nY = g_norm + (size_t)(cs*NMC + m)*NPTS + bx*128;
        cp16(sbuf + 33280u + (tid-32)*16, nY + (tid-32)*4);
    }
}

// Persistent fp8 warp-MMA Gram GEMM (neg terms). CTAs 0..63 fold in the
// analytic pos term. Epilogue: branchless max-certificate; exact rare path.
__global__ __launch_bounds__(256, 2) void k_dist(float* __restrict__ out) {
    extern __shared__ char smem[];
    __shared__ float red[8];
    uint32_t sb = smem_u32(smem);
    int tid  = threadIdx.x;
    int lane = tid & 31;
    int w    = tid >> 5;
    int warp_m = w & 3;     // 4 warps over M (32 rows each)
    int warp_n = w >> 2;    // 2 warps over N (64 cols each)

    prefetch_task((int)blockIdx.x, sb, tid);
    CP_COMMIT();

    // ---- pos term (exact, fp32): 512*(sum||xA||^2 + sum||xC||^2) - 2*SA.SC
    if (blockIdx.x < NMC) {
        int m = blockIdx.x;
        float u = 0.0f;
        if (tid < DDIM) {
            float sa = 0.0f, sc = 0.0f;
            #pragma unroll 4
            for (int ng = 0; ng < 16; ng++) {
                sa += g_part[((0*NMC + m)*16 + ng)*DDIM + tid];
                sc += g_part[((1*NMC + m)*16 + ng)*DDIM + tid];
            }
            u = -2.0f * sa * sc;
        }
        float ns = 0.0f;
        for (int i = tid; i < NPTS; i += 256) {
            ns += g_norm[(size_t)(0*NMC + m)*NPTS + i]
                + g_norm[(size_t)(2*NMC + m)*NPTS + i];
        }
        u = fmaf(512.0f, ns, u);
        #pragma unroll
        for (int o = 16; o; o >>= 1) u += __shfl_xor_sync(0xffffffffu, u, o);
        if (lane == 0) red[w] = u;
        __syncthreads();
        if (tid == 0) {
            float v = red[0] + red[1] + red[2] + red[3]
                    + red[4] + red[5] + red[6] + red[7];
            atomicAdd(&g_accum, (double)v);
        }
        __syncthreads();
    }

    float local = 0.0f;
    int it = 0;
    for (int t = (int)blockIdx.x; t < NTASK; t += GRID, it ^= 1) {
        int nxt = t + GRID;
        if (nxt < NTASK) prefetch_task(nxt, sb + (uint32_t)(it ^ 1) * BUFSZ, tid);
        CP_COMMIT();
        CP_WAIT1();
        __syncthreads();

        uint32_t bufA = sb + (uint32_t)it * BUFSZ;
        uint32_t bufB = bufA + 16384u;
        const float* xns = (const float*)(smem + it * BUFSZ + 32768);
        const float* yns = (const float*)(smem + it * BUFSZ + 33280);

        float acc[2][8][4];
        #pragma unroll
        for (int mt = 0; mt < 2; mt++)
            #pragma unroll
            for (int nt = 0; nt < 8; nt++)
                #pragma unroll
                for (int r = 0; r < 4; r++) acc[mt][nt][r] = 0.0f;

        #pragma unroll
        for (int ks = 0; ks < 4; ks++) {
            uint32_t a[2][4];
            #pragma unroll
            for (int mt = 0; mt < 2; mt++) {
                int r  = warp_m * 32 + mt * 16 + (lane & 15);
                int kb = ks * 32 + (lane >> 4) * 16;
                uint32_t addr = bufA + (uint32_t)(r * 128 + (((kb >> 4) ^ (r & 7)) << 4));
                ldmatrix_x4(a[mt], addr);
            }
            #pragma unroll
            for (int nt2 = 0; nt2 < 4; nt2++) {
                int r  = warp_n * 64 + nt2 * 16 + (lane & 7) + ((lane >> 4) << 3);
                int kb = ks * 32 + ((lane >> 3) & 1) * 16;
                uint32_t addr = bufB + (uint32_t)(r * 128 + (((kb >> 4) ^ (r & 7)) << 4));
                uint32_t tb[4];
                ldmatrix_x4(tb, addr);
                mma_fp8(acc[0][nt2*2],     a[0], &tb[0]);
                mma_fp8(acc[0][nt2*2 + 1], a[0], &tb[2]);
                mma_fp8(acc[1][nt2*2],     a[1], &tb[0]);
                mma_fp8(acc[1][nt2*2 + 1], a[1], &tb[2]);
            }
        }

        // Branchless certificate: any relu(2-d)>0 requires
        //   acc > px_i + py_j  (px = 0.5*xn-1, py = 0.5*yn-1).
        // Check max(acc) > min(px) + min(py) once; exact path only if it fires.
        float vmax = acc[0][0][0];
        #pragma unroll
        for (int mt = 0; mt < 2; mt++)
            #pragma unroll
            for (int nt = 0; nt < 8; nt++)
                #pragma unroll
                for (int r = 0; r < 4; r++)
                    vmax = fmaxf(vmax, acc[mt][nt][r]);

        int mb = warp_m * 32 + (lane >> 2);
        float pxmin = fminf(fminf(xns[mb], xns[mb + 8]),
                            fminf(xns[mb + 16], xns[mb + 24]));
        pxmin = fmaf(pxmin, 0.5f, -1.0f);
        int nb = warp_n * 64 + (lane & 3) * 2;
        float ymin = fminf(yns[nb], yns[nb + 1]);
        #pragma unroll
        for (int nt = 1; nt < 8; nt++)
            ymin = fminf(ymin, fminf(yns[nb + nt*8], yns[nb + nt*8 + 1]));
        float pymin = fmaf(ymin, 0.5f, -1.0f);

        if (vmax > pxmin + pymin) {   // rare exact path
            #pragma unroll
            for (int mt = 0; mt < 2; mt++) {
                int mbase = warp_m * 32 + mt * 16 + (lane >> 2);
                float px0 = fmaf(xns[mbase],     0.5f, -1.0f);
                float px1 = fmaf(xns[mbase + 8], 0.5f, -1.0f);
                #pragma unroll
                for (int nt = 0; nt < 8; nt++) {
                    int nbase = warp_n * 64 + nt * 8 + (lane & 3) * 2;
                    float py0 = fmaf(yns[nbase],     0.5f, -1.0f);
                    float py1 = fmaf(yns[nbase + 1], 0.5f, -1.0f);
                    float th[4] = {px0 + py0, px0 + py1, px1 + py0, px1 + py1};
                    #pragma unroll
                    for (int r = 0; r < 4; r++) {
                        if (acc[mt][nt][r] > th[r]) {
                            float d2 = 2.0f*(th[r] - acc[mt][nt][r]) + 4.0f;
                            float q = 2.0f - sqrtf(fmaxf(d2, 1e-12f));
                            local += q*q;
                        }
                    }
                }
            }
        }
        __syncthreads();
    }

    #pragma unroll
    for (int o = 16; o; o >>= 1) local += __shfl_xor_sync(0xffffffffu, local, o);
    if (lane == 0) red[w] = local;
    __syncthreads();
    if (tid == 0) {
        float v = red[0] + red[1] + red[2] + red[3]
                + red[4] + red[5] + red[6] + red[7];
        atomicAdd(&g_accum, (double)v);
        __threadfence();
        unsigned c = atomicAdd(&g_count, 1u);
        if (c == GRID - 1) {
            double total = atomicAdd(&g_accum, 0.0);
            out[0] = (float)(total * (1.0 / DENOM));
        }
    }
}

extern "C" void kernel_launch(void* const* d_in, const int* in_sizes, int n_in,
                              void* d_out, int out_size) {
    const float* mu    = (const float*)d_in[0];
    const float* sigma = (const float*)d_in[1];
    const float* epsA  = (const float*)d_in[2];
    const float* epsB  = (const float*)d_in[3];
    const float* epsC  = (const float*)d_in[4];
    (void)in_sizes; (void)n_in; (void)out_size;

    cudaFuncSetAttribute(k_dist, cudaFuncAttributeMaxDynamicSharedMemorySize, SM_TOTAL);

    k_gen<<<3*NMC*16, 256>>>(mu, sigma, epsA, epsB, epsC);
    k_dist<<<GRID, 256, SM_TOTAL>>>((float*)d_out);
}

// round 11
// speedup vs baseline: 2.9149x; 1.0429x over previous
#include <cuda_runtime.h>
#include <cuda_bf16.h>
#include <math.h>
#include <stdint.h>

#define NPTS 512
#define DDIM 128
#define NMC  64
#define DENOM 16777216.0
#define NTASK 2048
#define GRID  296

// Scratch (static device globals — no allocation allowed)
__device__ uint8_t g_Xf8[(size_t)3*NMC*NPTS*DDIM];   // 12.6MB e4m3
__device__ float   g_norm[3*NMC*NPTS];
__device__ float   g_part[2*NMC*16*DDIM];            // per-block row-sum partials, sets A/C
__device__ double  g_accum;
__device__ unsigned g_count;

__device__ __forceinline__ uint32_t smem_u32(const void* p) {
    uint32_t a;
    asm("{ .reg .u64 t; cvta.to.shared.u64 t, %1; cvt.u32.u64 %0, t; }" : "=r"(a) : "l"(p));
    return a;
}

__device__ __forceinline__ void ldmatrix_x4(uint32_t* r, uint32_t addr) {
    asm volatile("ldmatrix.sync.aligned.m8n8.x4.shared.b16 {%0,%1,%2,%3}, [%4];"
                 : "=r"(r[0]), "=r"(r[1]), "=r"(r[2]), "=r"(r[3]) : "r"(addr));
}

__device__ __forceinline__ void mma_fp8(float* c, const uint32_t* a, const uint32_t* b) {
    asm volatile(
        "mma.sync.aligned.m16n8k32.row.col.f32.e4m3.e4m3.f32 "
        "{%0,%1,%2,%3}, {%4,%5,%6,%7}, {%8,%9}, {%0,%1,%2,%3};"
        : "+f"(c[0]), "+f"(c[1]), "+f"(c[2]), "+f"(c[3])
        : "r"(a[0]), "r"(a[1]), "r"(a[2]), "r"(a[3]), "r"(b[0]), "r"(b[1]));
}

__device__ __forceinline__ void cp16(uint32_t dst, const void* src) {
    asm volatile("cp.async.cg.shared.global [%0], [%1], 16;"
                 :: "r"(dst), "l"(__cvta_generic_to_global(src)) : "memory");
}
#define CP_COMMIT() asm volatile("cp.async.commit_group;" ::: "memory")
#define CP_WAIT1()  asm volatile("cp.async.wait_group 1;"  ::: "memory")

__device__ __forceinline__ uint32_t pack4_e4m3(float x0, float x1, float x2, float x3) {
    uint16_t lo, hi;
    asm("cvt.rn.satfinite.e4m3x2.f32 %0, %1, %2;" : "=h"(lo) : "f"(x1), "f"(x0));
    asm("cvt.rn.satfinite.e4m3x2.f32 %0, %1, %2;" : "=h"(hi) : "f"(x3), "f"(x2));
    return (uint32_t)lo | ((uint32_t)hi << 16);
}

// ---- k_gen: x = mu + sigma*eps -> e4m3 X, fp32 norms, A/C row-sum partials.
// Block = 8 warps x 4 rows each = 32 rows of one (s, m). Grid = 3*64*16.
__global__ __launch_bounds__(256) void k_gen(
        const float* __restrict__ mu, const float* __restrict__ sigma,
        const float* __restrict__ epsA, const float* __restrict__ epsB,
        const float* __restrict__ epsC) {
    if (blockIdx.x == 0 && threadIdx.x == 0) { g_accum = 0.0; g_count = 0u; }
    int b  = blockIdx.x;
    int s  = b / (NMC * 16);
    int m  = (b / 16) % NMC;
    int ng = b % 16;
    int tid  = threadIdx.x;
    int wid  = tid >> 5;
    int lane = tid & 31;
    int n0 = ng * 32 + wid * 4;

    const float* eps = (s == 0) ? epsA : (s == 1) ? epsB : epsC;
    float4 a[4], g[4], e[4], x[4];
    #pragma unroll
    for (int r = 0; r < 4; r++) {
        a[r] = ((const float4*)(mu    + (size_t)(s*NPTS + n0 + r)*DDIM))[lane];
        g[r] = ((const float4*)(sigma + (size_t)(s*NPTS + n0 + r)*DDIM))[lane];
        e[r] = ((const float4*)(eps   + ((size_t)m*NPTS + n0 + r)*DDIM))[lane];
    }
    float ss[4];
    size_t row0 = (size_t)(s*NMC + m)*NPTS + n0;
    #pragma unroll
    for (int r = 0; r < 4; r++) {
        x[r].x = fmaf(g[r].x, e[r].x, a[r].x);
        x[r].y = fmaf(g[r].y, e[r].y, a[r].y);
        x[r].z = fmaf(g[r].z, e[r].z, a[r].z);
        x[r].w = fmaf(g[r].w, e[r].w, a[r].w);
        ((uint32_t*)(g_Xf8 + (row0 + r)*DDIM))[lane] =
            pack4_e4m3(x[r].x, x[r].y, x[r].z, x[r].w);
        ss[r] = x[r].x*x[r].x + x[r].y*x[r].y + x[r].z*x[r].z + x[r].w*x[r].w;
    }
    #pragma unroll
    for (int o = 16; o; o >>= 1) {
        #pragma unroll
        for (int r = 0; r < 4; r++) ss[r] += __shfl_xor_sync(0xffffffffu, ss[r], o);
    }
    if (lane == 0) {
        #pragma unroll
        for (int r = 0; r < 4; r++) g_norm[row0 + r] = ss[r];
    }

    if (s != 1) {   // partial row-sum vectors for the analytic pos term
        __shared__ float sx[32 * DDIM];
        #pragma unroll
        for (int r = 0; r < 4; r++)
            ((float4*)sx)[(wid*4 + r) * 32 + lane] = x[r];
        __syncthreads();
        if (tid < DDIM) {
            float acc = 0.0f;
            #pragma unroll
            for (int ww = 0; ww < 32; ww++) acc += sx[ww * DDIM + tid];
            int si = (s == 0) ? 0 : 1;
            g_part[((si*NMC + m)*16 + ng)*DDIM + tid] = acc;
        }
    }
}

// Per-buffer layout: A[0:16384) B[16384:32768) xn[32768:33280) yn[33280:33792)
#define BUFSZ 33792
#define SM_TOTAL (2*BUFSZ + 128)   // +128 for 128B alignment of buffer base

// Persistent fp8 warp-MMA Gram GEMM (neg terms). CTAs 0..63 fold in the
// analytic pos term. Hoisted swizzled addressing: ldmatrix addr = base^(ks<<5),
// prefetch offsets = {S0,D0} + i2*4096 (per-thread constants).
__global__ __launch_bounds__(256, 2) void k_dist(float* __restrict__ out) {
    extern __shared__ char smem[];
    __shared__ float red[8];
    uint32_t sbr = smem_u32(smem);
    uint32_t sb  = (sbr + 127u) & ~127u;           // 128B-aligned buffer base
    char* smc = smem + (sb - sbr);
    int tid  = threadIdx.x;
    int lane = tid & 31;
    int w    = tid >> 5;
    int warp_m = w & 3;     // 4 warps over M (32 rows each)
    int warp_n = w >> 2;    // 2 warps over N (64 cols each)

    // --- per-thread constant offsets ---
    // prefetch: row=(i2*32 + tid>>3), c=tid&7; row&7 == (tid>>3)&7 (i2-invariant)
    const uint32_t S0 = (uint32_t)((tid >> 3) * 128 + (tid & 7) * 16);
    const uint32_t D0 = (uint32_t)((tid >> 3) * 128 +
                         (((tid & 7) ^ ((tid >> 3) & 7)) << 4));
    // ldmatrix A: r = warp_m*32 + mt*16 + (lane&15); s = lane&7
    const uint32_t TA = (uint32_t)((warp_m * 32 + (lane & 15)) * 128 +
                         (((lane >> 4) ^ (lane & 1)) << 4) +
                         (((lane >> 1) & 3) << 5));
    // ldmatrix B: r = warp_n*64 + nt2*16 + (lane&7) + ((lane>>4)<<3); s = lane&7
    const uint32_t TB = (uint32_t)((warp_n * 64 + (lane & 7) + ((lane >> 4) << 3)) * 128 +
                         ((((lane >> 3) & 1) ^ (lane & 1)) << 4) +
                         (((lane >> 1) & 3) << 5));

    // --- prefetch (decode + hoisted offsets) ---
    auto prefetch = [&](int t, uint32_t sbuf) {
        int pp = t & 1;  int r1 = t >> 1;
        int m  = r1 & 63; int r2 = r1 >> 6;
        int bx = r2 & 3;  int by = r2 >> 2;
        const uint8_t* sX = g_Xf8 + (size_t)(64 + m) * 65536 + by * 16384 + S0;
        const uint8_t* sY = g_Xf8 + (size_t)(pp * 128 + m) * 65536 + bx * 16384 + S0;
        uint32_t dA = sbuf + D0;
        #pragma unroll
        for (int i2 = 0; i2 < 4; i2++) {
            cp16(dA + i2 * 4096,          sX + i2 * 4096);
            cp16(dA + 16384 + i2 * 4096,  sY + i2 * 4096);
        }
        if (tid < 32) {
            const float* nX = g_norm + (size_t)(64 + m) * NPTS + by * 128;
            cp16(sbuf + 32768u + tid * 16, nX + tid * 4);
        } else if (tid < 64) {
            const float* nY = g_norm + (size_t)(pp * 128 + m) * NPTS + bx * 128;
            cp16(sbuf + 33280u + (tid - 32) * 16, nY + (tid - 32) * 4);
        }
    };

    prefetch((int)blockIdx.x, sb);
    CP_COMMIT();

    // ---- pos term (exact, fp32): 512*(sum||xA||^2 + sum||xC||^2) - 2*SA.SC
    if (blockIdx.x < NMC) {
        int m = blockIdx.x;
        float u = 0.0f;
        if (tid < DDIM) {
            float sa = 0.0f, sc = 0.0f;
            #pragma unroll 4
            for (int ng = 0; ng < 16; ng++) {
                sa += g_part[((0*NMC + m)*16 + ng)*DDIM + tid];
                sc += g_part[((1*NMC + m)*16 + ng)*DDIM + tid];
            }
            u = -2.0f * sa * sc;
        }
        float ns = 0.0f;
        for (int i = tid; i < NPTS; i += 256) {
            ns += g_norm[(size_t)(0*NMC + m)*NPTS + i]
                + g_norm[(size_t)(2*NMC + m)*NPTS + i];
        }
        u = fmaf(512.0f, ns, u);
        #pragma unroll
        for (int o = 16; o; o >>= 1) u += __shfl_xor_sync(0xffffffffu, u, o);
        if (lane == 0) red[w] = u;
        __syncthreads();
        if (tid == 0) {
            float v = red[0] + red[1] + red[2] + red[3]
                    + red[4] + red[5] + red[6] + red[7];
            atomicAdd(&g_accum, (double)v);
        }
        __syncthreads();
    }

    float local = 0.0f;
    int it = 0;
    for (int t = (int)blockIdx.x; t < NTASK; t += GRID, it ^= 1) {
        int nxt = t + GRID;
        if (nxt < NTASK) prefetch(nxt, sb + (uint32_t)(it ^ 1) * BUFSZ);
        CP_COMMIT();
        CP_WAIT1();
        __syncthreads();

        uint32_t bufA = sb + (uint32_t)it * BUFSZ;
        uint32_t baseA = bufA + TA;
        uint32_t baseB = bufA + 16384u + TB;
        const float* xns = (const float*)(smc + it * BUFSZ + 32768);
        const float* yns = (const float*)(smc + it * BUFSZ + 33280);

        float acc[2][8][4];
        #pragma unroll
        for (int mt = 0; mt < 2; mt++)
            #pragma unroll
            for (int nt = 0; nt < 8; nt++)
                #pragma unroll
                for (int r = 0; r < 4; r++) acc[mt][nt][r] = 0.0f;

        #pragma unroll
        for (int ks = 0; ks < 4; ks++) {
            const uint32_t kx = (uint32_t)(ks << 5);
            uint32_t a[2][4];
            ldmatrix_x4(a[0],  baseA          ^ kx);
            ldmatrix_x4(a[1], (baseA + 2048u) ^ kx);
            #pragma unroll
            for (int nt2 = 0; nt2 < 4; nt2++) {
                uint32_t tb[4];
                ldmatrix_x4(tb, (baseB + (uint32_t)nt2 * 2048u) ^ kx);
                mma_fp8(acc[0][nt2*2],     a[0], &tb[0]);
                mma_fp8(acc[0][nt2*2 + 1], a[0], &tb[2]);
                mma_fp8(acc[1][nt2*2],     a[1], &tb[0]);
                mma_fp8(acc[1][nt2*2 + 1], a[1], &tb[2]);
            }
        }

        // Branchless certificate: any relu(2-d)>0 requires acc > px_i + py_j
        // (px = 0.5*xn-1, py = 0.5*yn-1). One compare; exact path if it fires.
        float vmax = acc[0][0][0];
        #pragma unroll
        for (int mt = 0; mt < 2; mt++)
            #pragma unroll
            for (int nt = 0; nt < 8; nt++)
                #pragma unroll
                for (int r = 0; r < 4; r++)
                    vmax = fmaxf(vmax, acc[mt][nt][r]);

        int mb = warp_m * 32 + (lane >> 2);
        float pxmin = fminf(fminf(xns[mb], xns[mb + 8]),
                            fminf(xns[mb + 16], xns[mb + 24]));
        pxmin = fmaf(pxmin, 0.5f, -1.0f);
        int nb = warp_n * 64 + (lane & 3) * 2;
        float ymin = fminf(yns[nb], yns[nb + 1]);
        #pragma unroll
        for (int nt = 1; nt < 8; nt++)
            ymin = fminf(ymin, fminf(yns[nb + nt*8], yns[nb + nt*8 + 1]));
        float pymin = fmaf(ymin, 0.5f, -1.0f);

        if (vmax > pxmin + pymin) {   // rare exact path
            #pragma unroll
            for (int mt = 0; mt < 2; mt++) {
                int mbase = warp_m * 32 + mt * 16 + (lane >> 2);
                float px0 = fmaf(xns[mbase],     0.5f, -1.0f);
                float px1 = fmaf(xns[mbase + 8], 0.5f, -1.0f);
                #pragma unroll
                for (int nt = 0; nt < 8; nt++) {
                    int nbase = warp_n * 64 + nt * 8 + (lane & 3) * 2;
                    float py0 = fmaf(yns[nbase],     0.5f, -1.0f);
                    float py1 = fmaf(yns[nbase + 1], 0.5f, -1.0f);
                    float th[4] = {px0 + py0, px0 + py1, px1 + py0, px1 + py1};
                    #pragma unroll
                    for (int r = 0; r < 4; r++) {
                        if (acc[mt][nt][r] > th[r]) {
                            float d2 = 2.0f*(th[r] - acc[mt][nt][r]) + 4.0f;
                            float q = 2.0f - sqrtf(fmaxf(d2, 1e-12f));
                            local += q*q;
                        }
                    }
                }
            }
        }
        __syncthreads();
    }

    #pragma unroll
    for (int o = 16; o; o >>= 1) local += __shfl_xor_sync(0xffffffffu, local, o);
    if (lane == 0) red[w] = local;
    __syncthreads();
    if (tid == 0) {
        float v = red[0] + red[1] + red[2] + red[3]
                + red[4] + red[5] + red[6] + red[7];
        atomicAdd(&g_accum, (double)v);
        __threadfence();
        unsigned c = atomicAdd(&g_count, 1u);
        if (c == GRID - 1) {
            double total = atomicAdd(&g_accum, 0.0);
            out[0] = (float)(total * (1.0 / DENOM));
        }
    }
}

extern "C" void kernel_launch(void* const* d_in, const int* in_sizes, int n_in,
                              void* d_out, int out_size) {
    const float* mu    = (const float*)d_in[0];
    const float* sigma = (const float*)d_in[1];
    const float* epsA  = (const float*)d_in[2];
    const float* epsB  = (const float*)d_in[3];
    const float* epsC  = (const float*)d_in[4];
    (void)in_sizes; (void)n_in; (void)out_size;

    cudaFuncSetAttribute(k_dist, cudaFuncAttributeMaxDynamicSharedMemorySize, SM_TOTAL);

    k_gen<<<3*NMC*16, 256>>>(mu, sigma, epsA, epsB, epsC);
    k_dist<<<GRID, 256, SM_TOTAL>>>((float*)d_out);
}

// round 12
// speedup vs baseline: 2.9351x; 1.0069x over previous
#include <cuda_runtime.h>
#include <cuda_bf16.h>
#include <math.h>
#include <stdint.h>

#define NPTS 512
#define DDIM 128
#define NMC  64
#define DENOM 16777216.0
#define NTASK 2048
#define GRID  296

// Scratch (static device globals — no allocation allowed)
__device__ uint8_t g_Xf8[(size_t)3*NMC*NPTS*DDIM];   // 12.6MB e4m3
__device__ float   g_norm[3*NMC*NPTS];
__device__ float   g_part[2*NMC*16*DDIM];            // per-block row-sum partials, sets A/C
__device__ double  g_accum;
__device__ unsigned g_count;

__device__ __forceinline__ uint32_t smem_u32(const void* p) {
    uint32_t a;
    asm("{ .reg .u64 t; cvta.to.shared.u64 t, %1; cvt.u32.u64 %0, t; }" : "=r"(a) : "l"(p));
    return a;
}

__device__ __forceinline__ void ldmatrix_x4(uint32_t* r, uint32_t addr) {
    asm volatile("ldmatrix.sync.aligned.m8n8.x4.shared.b16 {%0,%1,%2,%3}, [%4];"
                 : "=r"(r[0]), "=r"(r[1]), "=r"(r[2]), "=r"(r[3]) : "r"(addr));
}

__device__ __forceinline__ void mma_fp8(float* c, const uint32_t* a, const uint32_t* b) {
    asm volatile(
        "mma.sync.aligned.m16n8k32.row.col.f32.e4m3.e4m3.f32 "
        "{%0,%1,%2,%3}, {%4,%5,%6,%7}, {%8,%9}, {%0,%1,%2,%3};"
        : "+f"(c[0]), "+f"(c[1]), "+f"(c[2]), "+f"(c[3])
        : "r"(a[0]), "r"(a[1]), "r"(a[2]), "r"(a[3]), "r"(b[0]), "r"(b[1]));
}

__device__ __forceinline__ void cp16(uint32_t dst, const void* src) {
    asm volatile("cp.async.cg.shared.global [%0], [%1], 16;"
                 :: "r"(dst), "l"(__cvta_generic_to_global(src)) : "memory");
}
#define CP_COMMIT() asm volatile("cp.async.commit_group;" ::: "memory")
#define CP_WAIT1()  asm volatile("cp.async.wait_group 1;"  ::: "memory")

__device__ __forceinline__ uint32_t pack4_e4m3(float x0, float x1, float x2, float x3) {
    uint16_t lo, hi;
    asm("cvt.rn.satfinite.e4m3x2.f32 %0, %1, %2;" : "=h"(lo) : "f"(x1), "f"(x0));
    asm("cvt.rn.satfinite.e4m3x2.f32 %0, %1, %2;" : "=h"(hi) : "f"(x3), "f"(x2));
    return (uint32_t)lo | ((uint32_t)hi << 16);
}

// ---- k_gen: x = mu + sigma*eps -> e4m3 X, fp32 norms, A/C row-sum partials.
// Block = 8 warps x 4 rows each = 32 rows of one (s, m). Grid = 3*64*16.
__global__ __launch_bounds__(256) void k_gen(
        const float* __restrict__ mu, const float* __restrict__ sigma,
        const float* __restrict__ epsA, const float* __restrict__ epsB,
        const float* __restrict__ epsC) {
    if (blockIdx.x == 0 && threadIdx.x == 0) { g_accum = 0.0; g_count = 0u; }
    int b  = blockIdx.x;
    int s  = b / (NMC * 16);
    int m  = (b / 16) % NMC;
    int ng = b % 16;
    int tid  = threadIdx.x;
    int wid  = tid >> 5;
    int lane = tid & 31;
    int n0 = ng * 32 + wid * 4;

    const float* eps = (s == 0) ? epsA : (s == 1) ? epsB : epsC;
    float4 a[4], g[4], e[4], x[4];
    #pragma unroll
    for (int r = 0; r < 4; r++) {
        a[r] = ((const float4*)(mu    + (size_t)(s*NPTS + n0 + r)*DDIM))[lane];
        g[r] = ((const float4*)(sigma + (size_t)(s*NPTS + n0 + r)*DDIM))[lane];
        e[r] = ((const float4*)(eps   + ((size_t)m*NPTS + n0 + r)*DDIM))[lane];
    }
    float ss[4];
    size_t row0 = (size_t)(s*NMC + m)*NPTS + n0;
    #pragma unroll
    for (int r = 0; r < 4; r++) {
        x[r].x = fmaf(g[r].x, e[r].x, a[r].x);
        x[r].y = fmaf(g[r].y, e[r].y, a[r].y);
        x[r].z = fmaf(g[r].z, e[r].z, a[r].z);
        x[r].w = fmaf(g[r].w, e[r].w, a[r].w);
        ((uint32_t*)(g_Xf8 + (row0 + r)*DDIM))[lane] =
            pack4_e4m3(x[r].x, x[r].y, x[r].z, x[r].w);
        ss[r] = x[r].x*x[r].x + x[r].y*x[r].y + x[r].z*x[r].z + x[r].w*x[r].w;
    }
    #pragma unroll
    for (int o = 16; o; o >>= 1) {
        #pragma unroll
        for (int r = 0; r < 4; r++) ss[r] += __shfl_xor_sync(0xffffffffu, ss[r], o);
    }
    if (lane == 0) {
        #pragma unroll
        for (int r = 0; r < 4; r++) g_norm[row0 + r] = ss[r];
    }

    if (s != 1) {   // partial row-sum vectors for the analytic pos term
        __shared__ float sx[32 * DDIM];
        #pragma unroll
        for (int r = 0; r < 4; r++)
            ((float4*)sx)[(wid*4 + r) * 32 + lane] = x[r];
        __syncthreads();
        if (tid < DDIM) {
            float acc = 0.0f;
            #pragma unroll
            for (int ww = 0; ww < 32; ww++) acc += sx[ww * DDIM + tid];
            int si = (s == 0) ? 0 : 1;
            g_part[((si*NMC + m)*16 + ng)*DDIM + tid] = acc;
        }
    }
}

// Per-buffer layout: A[0:16384) B[16384:32768) xn[32768:33280) yn[33280:33792)
#define BUFSZ 33792
#define SM_TOTAL (2*BUFSZ + 128)   // +128 for 128B alignment of buffer base

// Persistent fp8 warp-MMA Gram GEMM (neg terms). CTAs 0..63 fold in the
// analytic pos term. Hoisted swizzled addressing; B-fragment LDSM double
// buffered so QMMAs never wait on the just-issued ldmatrix.
__global__ __launch_bounds__(256, 2) void k_dist(float* __restrict__ out) {
    extern __shared__ char smem[];
    __shared__ float red[8];
    uint32_t sbr = smem_u32(smem);
    uint32_t sb  = (sbr + 127u) & ~127u;           // 128B-aligned buffer base
    char* smc = smem + (sb - sbr);
    int tid  = threadIdx.x;
    int lane = tid & 31;
    int w    = tid >> 5;
    int warp_m = w & 3;     // 4 warps over M (32 rows each)
    int warp_n = w >> 2;    // 2 warps over N (64 cols each)

    // --- per-thread constant offsets ---
    const uint32_t S0 = (uint32_t)((tid >> 3) * 128 + (tid & 7) * 16);
    const uint32_t D0 = (uint32_t)((tid >> 3) * 128 +
                         (((tid & 7) ^ ((tid >> 3) & 7)) << 4));
    const uint32_t TA = (uint32_t)((warp_m * 32 + (lane & 15)) * 128 +
                         (((lane >> 4) ^ (lane & 1)) << 4) +
                         (((lane >> 1) & 3) << 5));
    const uint32_t TB = (uint32_t)((warp_n * 64 + (lane & 7) + ((lane >> 4) << 3)) * 128 +
                         ((((lane >> 3) & 1) ^ (lane & 1)) << 4) +
                         (((lane >> 1) & 3) << 5));

    auto prefetch = [&](int t, uint32_t sbuf) {
        int pp = t & 1;  int r1 = t >> 1;
        int m  = r1 & 63; int r2 = r1 >> 6;
        int bx = r2 & 3;  int by = r2 >> 2;
        const uint8_t* sX = g_Xf8 + (size_t)(64 + m) * 65536 + by * 16384 + S0;
        const uint8_t* sY = g_Xf8 + (size_t)(pp * 128 + m) * 65536 + bx * 16384 + S0;
        uint32_t dA = sbuf + D0;
        #pragma unroll
        for (int i2 = 0; i2 < 4; i2++) {
            cp16(dA + i2 * 4096,          sX + i2 * 4096);
            cp16(dA + 16384 + i2 * 4096,  sY + i2 * 4096);
        }
        if (tid < 32) {
            const float* nX = g_norm + (size_t)(64 + m) * NPTS + by * 128;
            cp16(sbuf + 32768u + tid * 16, nX + tid * 4);
        } else if (tid < 64) {
            const float* nY = g_norm + (size_t)(pp * 128 + m) * NPTS + bx * 128;
            cp16(sbuf + 33280u + (tid - 32) * 16, nY + (tid - 32) * 4);
        }
    };

    prefetch((int)blockIdx.x, sb);
    CP_COMMIT();

    // ---- pos term (exact, fp32): 512*(sum||xA||^2 + sum||xC||^2) - 2*SA.SC
    if (blockIdx.x < NMC) {
        int m = blockIdx.x;
        float u = 0.0f;
        if (tid < DDIM) {
            float sa = 0.0f, sc = 0.0f;
            #pragma unroll 4
            for (int ng = 0; ng < 16; ng++) {
                sa += g_part[((0*NMC + m)*16 + ng)*DDIM + tid];
                sc += g_part[((1*NMC + m)*16 + ng)*DDIM + tid];
            }
            u = -2.0f * sa * sc;
        }
        float ns = 0.0f;
        for (int i = tid; i < NPTS; i += 256) {
            ns += g_norm[(size_t)(0*NMC + m)*NPTS + i]
                + g_norm[(size_t)(2*NMC + m)*NPTS + i];
        }
        u = fmaf(512.0f, ns, u);
        #pragma unroll
        for (int o = 16; o; o >>= 1) u += __shfl_xor_sync(0xffffffffu, u, o);
        if (lane == 0) red[w] = u;
        __syncthreads();
        if (tid == 0) {
            float v = red[0] + red[1] + red[2] + red[3]
                    + red[4] + red[5] + red[6] + red[7];
            atomicAdd(&g_accum, (double)v);
        }
        __syncthreads();
    }

    float local = 0.0f;
    int it = 0;
    for (int t = (int)blockIdx.x; t < NTASK; t += GRID, it ^= 1) {
        int nxt = t + GRID;
        if (nxt < NTASK) prefetch(nxt, sb + (uint32_t)(it ^ 1) * BUFSZ);
        CP_COMMIT();
        CP_WAIT1();
        __syncthreads();

        uint32_t bufA = sb + (uint32_t)it * BUFSZ;
        uint32_t baseA = bufA + TA;
        uint32_t baseB = bufA + 16384u + TB;
        const float* xns = (const float*)(smc + it * BUFSZ + 32768);
        const float* yns = (const float*)(smc + it * BUFSZ + 33280);

        float acc[2][8][4];
        #pragma unroll
        for (int mt = 0; mt < 2; mt++)
            #pragma unroll
            for (int nt = 0; nt < 8; nt++)
                #pragma unroll
                for (int r = 0; r < 4; r++) acc[mt][nt][r] = 0.0f;

        // Software-pipelined fragment loads: tb double-buffered across the
        // 16 (ks,nt2) MMA groups; a reloaded once per ks.
        uint32_t a[2][4], tb[2][4];
        ldmatrix_x4(tb[0], baseB);          // (ks=0, nt2=0)
        #pragma unroll
        for (int ks = 0; ks < 4; ks++) {
            const uint32_t kx = (uint32_t)(ks << 5);
            ldmatrix_x4(a[0],  baseA          ^ kx);
            ldmatrix_x4(a[1], (baseA + 2048u) ^ kx);
            #pragma unroll
            for (int nt2 = 0; nt2 < 4; nt2++) {
                const int cur = nt2 & 1, nxtb = cur ^ 1;
                if (nt2 < 3) {
                    ldmatrix_x4(tb[nxtb], (baseB + (uint32_t)(nt2 + 1) * 2048u) ^ kx);
                } else if (ks < 3) {
                    ldmatrix_x4(tb[nxtb], baseB ^ (uint32_t)((ks + 1) << 5));
                }
                mma_fp8(acc[0][nt2*2],     a[0], &tb[cur][0]);
                mma_fp8(acc[0][nt2*2 + 1], a[0], &tb[cur][2]);
                mma_fp8(acc[1][nt2*2],     a[1], &tb[cur][0]);
                mma_fp8(acc[1][nt2*2 + 1], a[1], &tb[cur][2]);
            }
        }

        // Branchless certificate: any relu(2-d)>0 requires acc > px_i + py_j
        // (px = 0.5*xn-1, py = 0.5*yn-1). One compare; exact path if it fires.
        float vmax = acc[0][0][0];
        #pragma unroll
        for (int mt = 0; mt < 2; mt++)
            #pragma unroll
            for (int nt = 0; nt < 8; nt++)
                #pragma unroll
                for (int r = 0; r < 4; r++)
                    vmax = fmaxf(vmax, acc[mt][nt][r]);

        int mb = warp_m * 32 + (lane >> 2);
        float pxmin = fminf(fminf(xns[mb], xns[mb + 8]),
                            fminf(xns[mb + 16], xns[mb + 24]));
        pxmin = fmaf(pxmin, 0.5f, -1.0f);
        int nb = warp_n * 64 + (lane & 3) * 2;
        float ymin = fminf(yns[nb], yns[nb + 1]);
        #pragma unroll
        for (int nt = 1; nt < 8; nt++)
            ymin = fminf(ymin, fminf(yns[nb + nt*8], yns[nb + nt*8 + 1]));
        float pymin = fmaf(ymin, 0.5f, -1.0f);

        if (vmax > pxmin + pymin) {   // rare exact path
            #pragma unroll
            for (int mt = 0; mt < 2; mt++) {
                int mbase = warp_m * 32 + mt * 16 + (lane >> 2);
                float px0 = fmaf(xns[mbase],     0.5f, -1.0f);
                float px1 = fmaf(xns[mbase + 8], 0.5f, -1.0f);
                #pragma unroll
                for (int nt = 0; nt < 8; nt++) {
                    int nbase = warp_n * 64 + nt * 8 + (lane & 3) * 2;
                    float py0 = fmaf(yns[nbase],     0.5f, -1.0f);
                    float py1 = fmaf(yns[nbase + 1], 0.5f, -1.0f);
                    float th[4] = {px0 + py0, px0 + py1, px1 + py0, px1 + py1};
                    #pragma unroll
                    for (int r = 0; r < 4; r++) {
                        if (acc[mt][nt][r] > th[r]) {
                            float d2 = 2.0f*(th[r] - acc[mt][nt][r]) + 4.0f;
                            float q = 2.0f - sqrtf(fmaxf(d2, 1e-12f));
                            local += q*q;
                        }
                    }
                }
            }
        }
        __syncthreads();
    }

    #pragma unroll
    for (int o = 16; o; o >>= 1) local += __shfl_xor_sync(0xffffffffu, local, o);
    if (lane == 0) red[w] = local;
    __syncthreads();
    if (tid == 0) {
        float v = red[0] + red[1] + red[2] + red[3]
                + red[4] + red[5] + red[6] + red[7];
        atomicAdd(&g_accum, (double)v);
        __threadfence();
        unsigned c = atomicAdd(&g_count, 1u);
        if (c == GRID - 1) {
            double total = atomicAdd(&g_accum, 0.0);
            out[0] = (float)(total * (1.0 / DENOM));
        }
    }
}

extern "C" void kernel_launch(void* const* d_in, const int* in_sizes, int n_in,
                              void* d_out, int out_size) {
    const float* mu    = (const float*)d_in[0];
    const float* sigma = (const float*)d_in[1];
    const float* epsA  = (const float*)d_in[2];
    const float* epsB  = (const float*)d_in[3];
    const float* epsC  = (const float*)d_in[4];
    (void)in_sizes; (void)n_in; (void)out_size;

    cudaFuncSetAttribute(k_dist, cudaFuncAttributeMaxDynamicSharedMemorySize, SM_TOTAL);

    k_gen<<<3*NMC*16, 256>>>(mu, sigma, epsA, epsB, epsC);
    k_dist<<<GRID, 256, SM_TOTAL>>>((float*)d_out);
}